// round 4
// baseline (speedup 1.0000x reference)
#include <cuda_runtime.h>

// ---------------------------------------------------------------------------
// HierarchicalStageMoE — fp32 implementation with FFMA2 (f32x2) tiled GEMMs.
//
// Shapes: B*T = 8192 tokens, D=1024, F=64, DFE=128, RIN=1152, DRH=256,
//         NB=4, FPB=16, ES=4, NE=16, DEH=512.
// Outputs concatenated in d_out (float32), reference tuple order:
//   next_hidden[8192,1024], gate_weights[8192,16], gate_logits[8192,16],
//   bundle_weights[8192,4], bundle_logits[8192,4], stage_delta[8192,1024]
// ---------------------------------------------------------------------------

#define M_TOK 8192
#define D_HID 1024
#define F_FEAT 64
#define DFE 128
#define RIN 1152
#define DRH 256
#define NB 4
#define FPB 16
#define ES 4
#define NE 16
#define DEH 512
#define NEH (NE * DEH)  // 8192

#define OFF_NH 0
#define OFF_GW (M_TOK * D_HID)
#define OFF_GL (OFF_GW + M_TOK * NE)
#define OFF_BW (OFF_GL + M_TOK * NE)
#define OFF_BL (OFF_BW + M_TOK * NB)
#define OFF_SD (OFF_BL + M_TOK * NB)

typedef unsigned long long ull;

// ------------------------- scratch (static device memory) ------------------
__device__ float g_hnorm[M_TOK * D_HID];        // 32 MB
__device__ float g_sfe[M_TOK * DFE];            // 4 MB
__device__ float g_bemb[M_TOK * NB * DFE];      // 16 MB
__device__ float g_bh[M_TOK * DRH];             // 8 MB
__device__ float g_ih[M_TOK * NB * DRH];        // 32 MB
__device__ float g_gate[M_TOK * NE];            // 0.5 MB
__device__ float g_eh[(size_t)M_TOK * NEH];     // 268 MB (gate-scaled gelu(h@W1+b1))

// ------------------------- small helpers -----------------------------------
__device__ __forceinline__ float gelu_f(float x) {
    return 0.5f * x * (1.0f + erff(x * 0.70710678118654752440f));
}

__device__ __forceinline__ ull ffma2(ull a, ull b, ull c) {
    ull d;
    asm("fma.rn.f32x2 %0, %1, %2, %3;" : "=l"(d) : "l"(a), "l"(b), "l"(c));
    return d;
}
__device__ __forceinline__ ull pk2(float x, float y) {
    ull r;
    asm("mov.b64 %0, {%1, %2};" : "=l"(r) : "f"(x), "f"(y));
    return r;
}
__device__ __forceinline__ float2 upk2(ull v) {
    float2 r;
    asm("mov.b64 {%0, %1}, %2;" : "=f"(r.x), "=f"(r.y) : "l"(v));
    return r;
}

// ---------------------------------------------------------------------------
// Kernel 1: LayerNorm + stage feature embedding + per-bundle feature embedding
// ---------------------------------------------------------------------------
__global__ void __launch_bounds__(256) prep_kernel(
    const float* __restrict__ hidden, const float* __restrict__ feat,
    const float* __restrict__ ln_g, const float* __restrict__ ln_b,
    const float* __restrict__ stage_W, const float* __restrict__ stage_b,
    const float* __restrict__ bproj_W, const float* __restrict__ bproj_b)
{
    const int t = blockIdx.x;
    const int tid = threadIdx.x;
    __shared__ float red[256];
    __shared__ float sfeat[F_FEAT];

    const float* hrow = hidden + (size_t)t * D_HID;
    float x[4];
    float s = 0.f;
#pragma unroll
    for (int i = 0; i < 4; i++) { x[i] = hrow[tid + 256 * i]; s += x[i]; }
    if (tid < F_FEAT) sfeat[tid] = feat[(size_t)t * F_FEAT + tid];
    red[tid] = s;
    __syncthreads();
    for (int off = 128; off > 0; off >>= 1) {
        if (tid < off) red[tid] += red[tid + off];
        __syncthreads();
    }
    const float mu = red[0] * (1.0f / 1024.0f);
    __syncthreads();
    float v = 0.f;
#pragma unroll
    for (int i = 0; i < 4; i++) { float d = x[i] - mu; v += d * d; }
    red[tid] = v;
    __syncthreads();
    for (int off = 128; off > 0; off >>= 1) {
        if (tid < off) red[tid] += red[tid + off];
        __syncthreads();
    }
    const float rstd = rsqrtf(red[0] * (1.0f / 1024.0f) + 1e-5f);

#pragma unroll
    for (int i = 0; i < 4; i++) {
        int d = tid + 256 * i;
        g_hnorm[(size_t)t * D_HID + d] = (x[i] - mu) * rstd * ln_g[d] + ln_b[d];
    }
    // stage feature embedding: [64] @ [64,128] + b
    if (tid < DFE) {
        float acc = stage_b[tid];
#pragma unroll
        for (int f = 0; f < F_FEAT; f++) acc += sfeat[f] * stage_W[f * DFE + tid];
        g_sfe[(size_t)t * DFE + tid] = acc;
    }
    // bundle embeddings: per bundle g, [16] @ [16,128] + b
    for (int idx = tid; idx < NB * DFE; idx += 256) {
        int g = idx >> 7, j = idx & 127;
        float acc = bproj_b[g * DFE + j];
#pragma unroll
        for (int f = 0; f < FPB; f++)
            acc += sfeat[g * FPB + f] * bproj_W[(g * FPB + f) * DFE + j];
        g_bemb[(size_t)t * (NB * DFE) + idx] = acc;
    }
}

// ---------------------------------------------------------------------------
// Kernel 2/3: router GEMM1  (X = concat(h_norm, extra)) @ W1 + b1 -> gelu
// INTRA=0: bundle router (extra = g_sfe).  INTRA=1: z-th intra router.
// Tile 128x128x16, 256 threads, 8x8/thread via FFMA2.
// ---------------------------------------------------------------------------
template <int INTRA>
__global__ void __launch_bounds__(256) router_gemm(
    const float* __restrict__ W1, const float* __restrict__ b1)
{
    __shared__ float As[16][132];
    __shared__ float Bs[16][128];
    const int tid = threadIdx.x;
    const int tx = tid & 15, ty = tid >> 4;
    const int m0 = blockIdx.y * 128;
    const int n0 = blockIdx.x * 128;
    const int z = INTRA ? blockIdx.z : 0;

    const float* Wb = W1 + (size_t)z * (RIN * DRH);
    const float* bb = b1 + z * DRH;
    const float* extra = INTRA ? (g_bemb + z * DFE) : g_sfe;
    const int extra_ld = INTRA ? (NB * DFE) : DFE;
    float* ob = INTRA ? (g_ih + z * DRH) : g_bh;
    const int out_ld = INTRA ? (NB * DRH) : DRH;

    ull acc[8][4];
#pragma unroll
    for (int i = 0; i < 8; i++)
#pragma unroll
        for (int j = 0; j < 4; j++) acc[i][j] = 0ull;

    for (int k0 = 0; k0 < RIN; k0 += 16) {
#pragma unroll
        for (int l = 0; l < 2; l++) {
            int idx = l * 256 + tid;
            int row = idx >> 2, kq = idx & 3;
            int kg = k0 + kq * 4;
            float4 v;
            if (kg < D_HID)
                v = *(const float4*)&g_hnorm[(size_t)(m0 + row) * D_HID + kg];
            else
                v = *(const float4*)&extra[(size_t)(m0 + row) * extra_ld + (kg - D_HID)];
            As[kq * 4 + 0][row] = v.x; As[kq * 4 + 1][row] = v.y;
            As[kq * 4 + 2][row] = v.z; As[kq * 4 + 3][row] = v.w;
        }
#pragma unroll
        for (int l = 0; l < 2; l++) {
            int idx = l * 256 + tid;
            int kr = idx >> 5, nq = idx & 31;
            *(float4*)&Bs[kr][nq * 4] =
                *(const float4*)&Wb[(size_t)(k0 + kr) * DRH + n0 + nq * 4];
        }
        __syncthreads();
#pragma unroll
        for (int kk = 0; kk < 16; kk++) {
            float4 a0 = *(const float4*)&As[kk][ty * 4];
            float4 a1 = *(const float4*)&As[kk][64 + ty * 4];
            ull b00 = *(const ull*)&Bs[kk][tx * 4];
            ull b01 = *(const ull*)&Bs[kk][tx * 4 + 2];
            ull b10 = *(const ull*)&Bs[kk][64 + tx * 4];
            ull b11 = *(const ull*)&Bs[kk][64 + tx * 4 + 2];
            float ar[8] = {a0.x, a0.y, a0.z, a0.w, a1.x, a1.y, a1.z, a1.w};
#pragma unroll
            for (int i = 0; i < 8; i++) {
                ull a2 = pk2(ar[i], ar[i]);
                acc[i][0] = ffma2(a2, b00, acc[i][0]);
                acc[i][1] = ffma2(a2, b01, acc[i][1]);
                acc[i][2] = ffma2(a2, b10, acc[i][2]);
                acc[i][3] = ffma2(a2, b11, acc[i][3]);
            }
        }
        __syncthreads();
    }
#pragma unroll
    for (int i = 0; i < 8; i++) {
        int row = m0 + ((i < 4) ? (ty * 4 + i) : (64 + ty * 4 + (i - 4)));
#pragma unroll
        for (int j2 = 0; j2 < 4; j2++) {
            int c = (j2 < 2) ? (tx * 4 + j2 * 2) : (64 + tx * 4 + (j2 - 2) * 2);
            int n = n0 + c;
            float2 v = upk2(acc[i][j2]);
            float2 o;
            o.x = gelu_f(v.x + bb[n]);
            o.y = gelu_f(v.y + bb[n + 1]);
            *(float2*)&ob[(size_t)row * out_ld + n] = o;
        }
    }
}

// ---------------------------------------------------------------------------
// Kernel 4: bundle+intra logits, top-2 softmaxes, gate weights/logits outputs
// ---------------------------------------------------------------------------
__device__ __forceinline__ void top2sm4(const float* s, float* w) {
    float m1 = fmaxf(fmaxf(s[0], s[1]), fmaxf(s[2], s[3]));
    float m2 = -3.0e38f;
    bool used = false;
#pragma unroll
    for (int i = 0; i < 4; i++) {
        if (!used && s[i] == m1) used = true;
        else m2 = fmaxf(m2, s[i]);
    }
    float e[4];
    float den = 0.f;
#pragma unroll
    for (int i = 0; i < 4; i++) {
        e[i] = (s[i] >= m2) ? expf(s[i] - m1) : 0.f;
        den += e[i];
    }
    float inv = 1.0f / den;
#pragma unroll
    for (int i = 0; i < 4; i++) w[i] = e[i] * inv;
}

__global__ void __launch_bounds__(128) gate_kernel(
    const float* __restrict__ br_W2, const float* __restrict__ br_b2,
    const float* __restrict__ ir_W2, const float* __restrict__ ir_b2,
    float* __restrict__ out)
{
    const int t = blockIdx.x;
    const int tid = threadIdx.x;
    __shared__ float sbh[DRH];
    __shared__ float sih[NB * DRH];
    __shared__ float slog[20];

    for (int i = tid; i < DRH; i += 128) sbh[i] = g_bh[(size_t)t * DRH + i];
    for (int i = tid; i < NB * DRH; i += 128) sih[i] = g_ih[(size_t)t * NB * DRH + i];
    __syncthreads();

    const int w = tid >> 5, lane = tid & 31;
    for (int d = w; d < 20; d += 4) {
        float s = 0.f;
        if (d < 4) {
            for (int k = lane; k < DRH; k += 32) s += sbh[k] * br_W2[k * NB + d];
        } else {
            int g = (d - 4) >> 2, e = (d - 4) & 3;
            const float* w2 = ir_W2 + g * DRH * ES;
            const float* ihg = sih + g * DRH;
            for (int k = lane; k < DRH; k += 32) s += ihg[k] * w2[k * ES + e];
        }
#pragma unroll
        for (int off = 16; off; off >>= 1) s += __shfl_xor_sync(0xffffffffu, s, off);
        if (lane == 0) slog[d] = s + ((d < 4) ? br_b2[d] : ir_b2[d - 4]);
    }
    __syncthreads();

    if (tid == 0) {
        float bl[4], bw[4], il[16], iw[16];
#pragma unroll
        for (int i = 0; i < 4; i++) bl[i] = slog[i];
#pragma unroll
        for (int i = 0; i < 16; i++) il[i] = slog[4 + i];
        top2sm4(bl, bw);
#pragma unroll
        for (int g = 0; g < 4; g++) top2sm4(&il[g * 4], &iw[g * 4]);
#pragma unroll
        for (int g = 0; g < 4; g++) {
            out[OFF_BW + (size_t)t * NB + g] = bw[g];
            out[OFF_BL + (size_t)t * NB + g] = bl[g];
#pragma unroll
            for (int e = 0; e < 4; e++) {
                int idx = g * 4 + e;
                float gw = bw[g] * iw[idx];
                out[OFF_GW + (size_t)t * NE + idx] = gw;
                out[OFF_GL + (size_t)t * NE + idx] = bl[g] + il[idx];
                g_gate[(size_t)t * NE + idx] = gw;
            }
        }
    }
}

// ---------------------------------------------------------------------------
// Kernel 5: expert GEMM1  eh[t, e*512+h] = gate[t,e]*gelu(h_norm@W1[e] + b1)
// N = 16*512 = 8192 columns; each 128-col tile lies inside one expert.
// ---------------------------------------------------------------------------
__global__ void __launch_bounds__(256) ex1_gemm(
    const float* __restrict__ ex_W1, const float* __restrict__ ex_b1)
{
    __shared__ float As[16][132];
    __shared__ float Bs[16][128];
    const int tid = threadIdx.x;
    const int tx = tid & 15, ty = tid >> 4;
    const int m0 = blockIdx.y * 128;
    const int n0g = blockIdx.x * 128;
    const int e = n0g >> 9;
    const int c0 = n0g & 511;
    const float* Bb = ex_W1 + (size_t)e * (D_HID * DEH) + c0;

    ull acc[8][4];
#pragma unroll
    for (int i = 0; i < 8; i++)
#pragma unroll
        for (int j = 0; j < 4; j++) acc[i][j] = 0ull;

    for (int k0 = 0; k0 < D_HID; k0 += 16) {
#pragma unroll
        for (int l = 0; l < 2; l++) {
            int idx = l * 256 + tid;
            int row = idx >> 2, kq = idx & 3;
            float4 v = *(const float4*)&g_hnorm[(size_t)(m0 + row) * D_HID + k0 + kq * 4];
            As[kq * 4 + 0][row] = v.x; As[kq * 4 + 1][row] = v.y;
            As[kq * 4 + 2][row] = v.z; As[kq * 4 + 3][row] = v.w;
        }
#pragma unroll
        for (int l = 0; l < 2; l++) {
            int idx = l * 256 + tid;
            int kr = idx >> 5, nq = idx & 31;
            *(float4*)&Bs[kr][nq * 4] =
                *(const float4*)&Bb[(size_t)(k0 + kr) * DEH + nq * 4];
        }
        __syncthreads();
#pragma unroll
        for (int kk = 0; kk < 16; kk++) {
            float4 a0 = *(const float4*)&As[kk][ty * 4];
            float4 a1 = *(const float4*)&As[kk][64 + ty * 4];
            ull b00 = *(const ull*)&Bs[kk][tx * 4];
            ull b01 = *(const ull*)&Bs[kk][tx * 4 + 2];
            ull b10 = *(const ull*)&Bs[kk][64 + tx * 4];
            ull b11 = *(const ull*)&Bs[kk][64 + tx * 4 + 2];
            float ar[8] = {a0.x, a0.y, a0.z, a0.w, a1.x, a1.y, a1.z, a1.w};
#pragma unroll
            for (int i = 0; i < 8; i++) {
                ull a2 = pk2(ar[i], ar[i]);
                acc[i][0] = ffma2(a2, b00, acc[i][0]);
                acc[i][1] = ffma2(a2, b01, acc[i][1]);
                acc[i][2] = ffma2(a2, b10, acc[i][2]);
                acc[i][3] = ffma2(a2, b11, acc[i][3]);
            }
        }
        __syncthreads();
    }
#pragma unroll
    for (int i = 0; i < 8; i++) {
        int row = m0 + ((i < 4) ? (ty * 4 + i) : (64 + ty * 4 + (i - 4)));
        float gv = g_gate[(size_t)row * NE + e];
#pragma unroll
        for (int j2 = 0; j2 < 4; j2++) {
            int c = (j2 < 2) ? (tx * 4 + j2 * 2) : (64 + tx * 4 + (j2 - 2) * 2);
            int ng = n0g + c;
            float2 v = upk2(acc[i][j2]);
            float2 o;
            o.x = gelu_f(v.x + ex_b1[ng]) * gv;   // ex_b1 is flat [16*512]
            o.y = gelu_f(v.y + ex_b1[ng + 1]) * gv;
            *(float2*)&g_eh[(size_t)row * NEH + ng] = o;
        }
    }
}

// ---------------------------------------------------------------------------
// Kernel 6: expert GEMM2 + combine.
// delta[t,d] = sum_{e,k} eh_scaled[t,e*512+k] * W2[e,k,d] + sum_e g[t,e]*b2[e,d]
// ex_W2 [16,512,1024] flattens to a plain [8192,1024] row-major B.
// next_hidden = hidden + alpha*delta. Writes both big outputs.
// ---------------------------------------------------------------------------
__global__ void __launch_bounds__(256) ex2_gemm(
    const float* __restrict__ ex_W2, const float* __restrict__ ex_b2,
    const float* __restrict__ hidden, const float* __restrict__ alpha_p,
    float* __restrict__ out)
{
    __shared__ float As[16][132];
    __shared__ float Bs[16][128];
    const int tid = threadIdx.x;
    const int tx = tid & 15, ty = tid >> 4;
    const int m0 = blockIdx.y * 128;
    const int n0 = blockIdx.x * 128;

    ull acc[8][4];
#pragma unroll
    for (int i = 0; i < 8; i++)
#pragma unroll
        for (int j = 0; j < 4; j++) acc[i][j] = 0ull;

    for (int k0 = 0; k0 < NEH; k0 += 16) {
#pragma unroll
        for (int l = 0; l < 2; l++) {
            int idx = l * 256 + tid;
            int row = idx >> 2, kq = idx & 3;
            float4 v = *(const float4*)&g_eh[(size_t)(m0 + row) * NEH + k0 + kq * 4];
            As[kq * 4 + 0][row] = v.x; As[kq * 4 + 1][row] = v.y;
            As[kq * 4 + 2][row] = v.z; As[kq * 4 + 3][row] = v.w;
        }
#pragma unroll
        for (int l = 0; l < 2; l++) {
            int idx = l * 256 + tid;
            int kr = idx >> 5, nq = idx & 31;
            *(float4*)&Bs[kr][nq * 4] =
                *(const float4*)&ex_W2[(size_t)(k0 + kr) * D_HID + n0 + nq * 4];
        }
        __syncthreads();
#pragma unroll
        for (int kk = 0; kk < 16; kk++) {
            float4 a0 = *(const float4*)&As[kk][ty * 4];
            float4 a1 = *(const float4*)&As[kk][64 + ty * 4];
            ull b00 = *(const ull*)&Bs[kk][tx * 4];
            ull b01 = *(const ull*)&Bs[kk][tx * 4 + 2];
            ull b10 = *(const ull*)&Bs[kk][64 + tx * 4];
            ull b11 = *(const ull*)&Bs[kk][64 + tx * 4 + 2];
            float ar[8] = {a0.x, a0.y, a0.z, a0.w, a1.x, a1.y, a1.z, a1.w};
#pragma unroll
            for (int i = 0; i < 8; i++) {
                ull a2 = pk2(ar[i], ar[i]);
                acc[i][0] = ffma2(a2, b00, acc[i][0]);
                acc[i][1] = ffma2(a2, b01, acc[i][1]);
                acc[i][2] = ffma2(a2, b10, acc[i][2]);
                acc[i][3] = ffma2(a2, b11, acc[i][3]);
            }
        }
        __syncthreads();
    }

    const float alpha = *alpha_p;
#pragma unroll
    for (int i = 0; i < 8; i++) {
        int row = m0 + ((i < 4) ? (ty * 4 + i) : (64 + ty * 4 + (i - 4)));
        float g16[16];
#pragma unroll
        for (int e = 0; e < NE; e++) g16[e] = g_gate[(size_t)row * NE + e];
#pragma unroll
        for (int j2 = 0; j2 < 4; j2++) {
            int c = (j2 < 2) ? (tx * 4 + j2 * 2) : (64 + tx * 4 + (j2 - 2) * 2);
            int n = n0 + c;
            float2 v = upk2(acc[i][j2]);
            float b0 = 0.f, b1v = 0.f;
#pragma unroll
            for (int e = 0; e < NE; e++) {
                b0  = fmaf(g16[e], ex_b2[e * D_HID + n], b0);
                b1v = fmaf(g16[e], ex_b2[e * D_HID + n + 1], b1v);
            }
            float d0 = v.x + b0;
            float d1 = v.y + b1v;
            float2 h = *(const float2*)&hidden[(size_t)row * D_HID + n];
            float2 nh; nh.x = h.x + alpha * d0; nh.y = h.y + alpha * d1;
            float2 sd; sd.x = d0; sd.y = d1;
            *(float2*)&out[OFF_NH + (size_t)row * D_HID + n] = nh;
            *(float2*)&out[OFF_SD + (size_t)row * D_HID + n] = sd;
        }
    }
}

// ---------------------------------------------------------------------------
// launch
// ---------------------------------------------------------------------------
extern "C" void kernel_launch(void* const* d_in, const int* in_sizes, int n_in,
                              void* d_out, int out_size)
{
    const float* hidden  = (const float*)d_in[0];
    const float* feat    = (const float*)d_in[1];
    const float* ln_g    = (const float*)d_in[2];
    const float* ln_b    = (const float*)d_in[3];
    const float* stage_W = (const float*)d_in[4];
    const float* stage_b = (const float*)d_in[5];
    const float* bproj_W = (const float*)d_in[6];
    const float* bproj_b = (const float*)d_in[7];
    const float* br_W1   = (const float*)d_in[8];
    const float* br_b1   = (const float*)d_in[9];
    const float* br_W2   = (const float*)d_in[10];
    const float* br_b2   = (const float*)d_in[11];
    const float* ir_W1   = (const float*)d_in[12];
    const float* ir_b1   = (const float*)d_in[13];
    const float* ir_W2   = (const float*)d_in[14];
    const float* ir_b2   = (const float*)d_in[15];
    const float* ex_W1   = (const float*)d_in[16];
    const float* ex_b1   = (const float*)d_in[17];
    const float* ex_W2   = (const float*)d_in[18];
    const float* ex_b2   = (const float*)d_in[19];
    const float* alpha   = (const float*)d_in[20];
    float* out = (float*)d_out;

    prep_kernel<<<M_TOK, 256>>>(hidden, feat, ln_g, ln_b,
                                stage_W, stage_b, bproj_W, bproj_b);

    {
        dim3 g(DRH / 128, M_TOK / 128, 1);
        router_gemm<0><<<g, 256>>>(br_W1, br_b1);
    }
    {
        dim3 g(DRH / 128, M_TOK / 128, NB);
        router_gemm<1><<<g, 256>>>(ir_W1, ir_b1);
    }

    gate_kernel<<<M_TOK, 128>>>(br_W2, br_b2, ir_W2, ir_b2, out);

    {
        dim3 g(NEH / 128, M_TOK / 128, 1);
        ex1_gemm<<<g, 256>>>(ex_W1, ex_b1);
    }
    {
        dim3 g(D_HID / 128, M_TOK / 128, 1);
        ex2_gemm<<<g, 256>>>(ex_W2, ex_b2, hidden, alpha, out);
    }
}